// round 6
// baseline (speedup 1.0000x reference)
#include <cuda_runtime.h>
#include <cuda_bf16.h>
#include <mma.h>
#include <math.h>
#include <stdint.h>

using namespace nvcuda;

// Problem constants
#define DDIM 1024
#define NEXP 8
#define HDIM 4096
#define TOPK 2
#define NTOK 8192               // B*S
#define NROWS (NTOK * TOPK)     // 16384

// WMMA fast-path tile: 128(M) x 128(N) x 32(K) per CTA, 8 warps, 48KB static smem
#define TM 128
#define TN 128
#define KC 32
#define PADK 48                 // padded k-stride (elements); 96B rows, 16B aligned
#define SBUF (128 * PADK)       // elements per buffer

// Fallback (R1-proven) tile
#define FBM 128
#define FBN 128
#define FBK 16

// ---------------- scratch (device globals; no runtime allocation) -------------
__device__ __nv_bfloat16 g_xhi[(size_t)NTOK * DDIM];
__device__ __nv_bfloat16 g_xlo[(size_t)NTOK * DDIM];
__device__ __nv_bfloat16 g_w1hi[(size_t)NEXP * HDIM * DDIM];   // [E][N=H][K=D]
__device__ __nv_bfloat16 g_w1lo[(size_t)NEXP * HDIM * DDIM];
__device__ __nv_bfloat16 g_w2hi[(size_t)NEXP * DDIM * HDIM];   // [E][N=D][K=H]
__device__ __nv_bfloat16 g_w2lo[(size_t)NEXP * DDIM * HDIM];
__device__ __nv_bfloat16 g_hhi[(size_t)NROWS * HDIM];
__device__ __nv_bfloat16 g_hlo[(size_t)NROWS * HDIM];
__device__ float g_oscr[(size_t)NROWS * DDIM];
__device__ int   g_rows_token[NROWS];
__device__ int   g_rows_dest[NROWS];
__device__ float g_wslot[NROWS];
__device__ int   g_tok_eidx[NROWS];
__device__ int   g_counts[NEXP];
__device__ int   g_offsets[NEXP + 1];
__device__ int   g_tileoff[NEXP + 1];
__device__ int   g_fill[NEXP];
__device__ int   g_flag1;   // 1 = g_hhi looks dead -> fallback GEMM1 runs
__device__ int   g_flag2;   // 1 = g_oscr looks dead -> fallback GEMM2 runs

// ---------------- helpers ------------------------------------------------------
__device__ __forceinline__ void bsplit(float v, uint16_t& h, uint16_t& l) {
    __nv_bfloat16 hb = __float2bfloat16(v);
    __nv_bfloat16 lb = __float2bfloat16(v - __bfloat162float(hb));
    h = __bfloat16_as_ushort(hb);
    l = __bfloat16_as_ushort(lb);
}
__device__ __forceinline__ float bf_lo(uint32_t u) {
    return __bfloat162float(__ushort_as_bfloat16((unsigned short)(u & 0xFFFF)));
}
__device__ __forceinline__ float bf_hi(uint32_t u) {
    return __bfloat162float(__ushort_as_bfloat16((unsigned short)(u >> 16)));
}
__device__ __forceinline__ float gelu_exact(float v) {
    return 0.5f * v * (1.0f + erff(v * 0.70710678118654752440f));
}

// ---------------- gating (proven) -----------------------------------------------
__global__ void reset_kernel() {
    int i = threadIdx.x;
    if (i < NEXP) g_counts[i] = 0;
    if (i == 0) { g_flag1 = 1; g_flag2 = 1; }
}

__global__ void gate_kernel(const float* __restrict__ x, const float* __restrict__ gw) {
    int warp = (blockIdx.x * blockDim.x + threadIdx.x) >> 5;
    int lane = threadIdx.x & 31;
    if (warp >= NTOK) return;
    const float* xr = x + (size_t)warp * DDIM;

    float acc[NEXP];
#pragma unroll
    for (int e = 0; e < NEXP; e++) acc[e] = 0.f;
    for (int d = lane; d < DDIM; d += 32) {
        float xv = xr[d];
        const float* g = gw + (size_t)d * NEXP;
#pragma unroll
        for (int e = 0; e < NEXP; e++) acc[e] = fmaf(xv, g[e], acc[e]);
    }
#pragma unroll
    for (int e = 0; e < NEXP; e++) {
#pragma unroll
        for (int o = 16; o > 0; o >>= 1)
            acc[e] += __shfl_xor_sync(0xffffffff, acc[e], o);
    }
    if (lane == 0) {
        int b0 = 0; float s0 = acc[0];
#pragma unroll
        for (int e = 1; e < NEXP; e++) if (acc[e] > s0) { s0 = acc[e]; b0 = e; }
        int b1 = -1; float s1 = -INFINITY;
#pragma unroll
        for (int e = 0; e < NEXP; e++)
            if (e != b0 && acc[e] > s1) { s1 = acc[e]; b1 = e; }
        float p = expf(s1 - s0);
        float inv = 1.0f / (1.0f + p);
        g_tok_eidx[warp * 2 + 0] = b0;
        g_tok_eidx[warp * 2 + 1] = b1;
        g_wslot[warp * 2 + 0] = inv;
        g_wslot[warp * 2 + 1] = p * inv;
        atomicAdd(&g_counts[b0], 1);
        atomicAdd(&g_counts[b1], 1);
    }
}

__global__ void scan_kernel() {
    int s = 0, ts = 0;
    for (int e = 0; e < NEXP; e++) {
        g_offsets[e] = s;
        g_tileoff[e] = ts;
        s += g_counts[e];
        ts += (g_counts[e] + TM - 1) / TM;
        g_fill[e] = 0;
    }
    g_offsets[NEXP] = s;
    g_tileoff[NEXP] = ts;
}

__global__ void build_kernel() {
    int t = blockIdx.x * blockDim.x + threadIdx.x;
    if (t >= NTOK) return;
#pragma unroll
    for (int k = 0; k < TOPK; k++) {
        int e = g_tok_eidx[t * 2 + k];
        int pos = g_offsets[e] + atomicAdd(&g_fill[e], 1);
        g_rows_token[pos] = t;
        g_rows_dest[pos] = t * 2 + k;
    }
}

// ---------------- fp32 -> bf16 hi/lo splits -----------------------------------
__global__ void split_x_kernel(const float* __restrict__ x) {
    size_t i = (size_t)blockIdx.x * blockDim.x + threadIdx.x;
    float4 v = reinterpret_cast<const float4*>(x)[i];
    float f[4] = {v.x, v.y, v.z, v.w};
    uint32_t hp[2], lp[2];
#pragma unroll
    for (int j = 0; j < 2; j++) {
        uint16_t h0, l0, h1, l1;
        bsplit(f[2 * j + 0], h0, l0);
        bsplit(f[2 * j + 1], h1, l1);
        hp[j] = (uint32_t)h0 | ((uint32_t)h1 << 16);
        lp[j] = (uint32_t)l0 | ((uint32_t)l1 << 16);
    }
    reinterpret_cast<uint2*>(g_xhi)[i] = make_uint2(hp[0], hp[1]);
    reinterpret_cast<uint2*>(g_xlo)[i] = make_uint2(lp[0], lp[1]);
}

// w [E][K][N] fp32 -> wT hi/lo [E][N][K] bf16 (transpose + split)
__global__ void split_wT_kernel(const float* __restrict__ w,
                                __nv_bfloat16* __restrict__ whi,
                                __nv_bfloat16* __restrict__ wlo,
                                int K, int N) {
    __shared__ float tile[32][33];
    int e = blockIdx.z;
    int n0 = blockIdx.x * 32, k0 = blockIdx.y * 32;
    const float* we = w + (size_t)e * K * N;
    int tx = threadIdx.x, ty = threadIdx.y;
#pragma unroll
    for (int r = ty; r < 32; r += 8)
        tile[r][tx] = we[(size_t)(k0 + r) * N + n0 + tx];
    __syncthreads();
    size_t obase = (size_t)e * N * K;
#pragma unroll
    for (int r = ty; r < 32; r += 8) {
        float v = tile[tx][r];
        uint16_t h, l;
        bsplit(v, h, l);
        size_t o = obase + (size_t)(n0 + r) * K + (k0 + tx);
        whi[o] = __ushort_as_bfloat16(h);
        wlo[o] = __ushort_as_bfloat16(l);
    }
}

// ---------------- FAST grouped GEMM via nvcuda::wmma (split-bf16, 3 passes) ----
// MODE 1: A = x (gathered hi/lo), B = w1T[e] [N=H][K=D], +b1, GELU -> g_h hi/lo
// MODE 2: A = g_h (contig rows),  B = w2T[e] [N=D][K=H], +b2 -> g_oscr[slot]
template <int MODE>
__global__ __launch_bounds__(256)
void moe_gemm_wmma(const float* __restrict__ bias) {
    constexpr int KDIM = (MODE == 1) ? DDIM : HDIM;
    constexpr int NDIM = (MODE == 1) ? HDIM : DDIM;
    constexpr int NCH = KDIM / KC;

    // 4 buffers x 128 rows x PADK(48) bf16 = 49152 bytes (static max)
    __shared__ __align__(16) __nv_bfloat16 sm[4 * SBUF];
    __nv_bfloat16* sAh = sm;
    __nv_bfloat16* sAl = sm + SBUF;
    __nv_bfloat16* sBh = sm + 2 * SBUF;
    __nv_bfloat16* sBl = sm + 3 * SBUF;

    int t = blockIdx.y;
    if (t >= g_tileoff[NEXP]) return;
    int e = 0;
#pragma unroll
    for (int i = 0; i < NEXP - 1; i++)
        if (t >= g_tileoff[i + 1]) e = i + 1;
    int roff = g_offsets[e];
    int cnt = g_offsets[e + 1] - roff;
    int m0 = (t - g_tileoff[e]) * TM;
    int n0 = blockIdx.x * TN;

    int tid = threadIdx.x;
    int wid = tid >> 5, lane = tid & 31;
    int wm = wid & 1;            // m offset: wm*64, 4 m-frags
    int wn = wid >> 1;           // n offset: wn*32, 2 n-frags

    const __nv_bfloat16* Ahi_g = (MODE == 1) ? g_xhi : g_hhi;
    const __nv_bfloat16* Alo_g = (MODE == 1) ? g_xlo : g_hlo;
    const __nv_bfloat16* Bhi_e = ((MODE == 1) ? g_w1hi : g_w2hi) + (size_t)e * NDIM * KDIM;
    const __nv_bfloat16* Blo_e = ((MODE == 1) ? g_w1lo : g_w2lo) + (size_t)e * NDIM * KDIM;

    // --- staging geometry: thread covers rows (tid>>2) and 64+(tid>>2), col chunk tid&3
    int lc4 = tid & 3;
    int r0 = tid >> 2;
    int r1 = 64 + r0;
    int src0, src1;
    if (MODE == 1) {
        src0 = (m0 + r0 < cnt) ? g_rows_token[roff + m0 + r0] : 0;
        src1 = (m0 + r1 < cnt) ? g_rows_token[roff + m0 + r1] : 0;
    } else {
        int a0g = roff + m0 + r0, a1g = roff + m0 + r1;
        src0 = (a0g < NROWS) ? a0g : (NROWS - 1);
        src1 = (a1g < NROWS) ? a1g : (NROWS - 1);
    }
    size_t aoff0 = (size_t)src0 * KDIM + lc4 * 8;
    size_t aoff1 = (size_t)src1 * KDIM + lc4 * 8;
    size_t boff0 = (size_t)(n0 + r0) * KDIM + lc4 * 8;
    size_t boff1 = (size_t)(n0 + r1) * KDIM + lc4 * 8;
    int s0 = r0 * PADK + lc4 * 8;   // element offsets; byte-aligned to 16
    int s1 = r1 * PADK + lc4 * 8;

    wmma::fragment<wmma::accumulator, 16, 16, 16, float> acc[4][2];
#pragma unroll
    for (int mf = 0; mf < 4; mf++)
#pragma unroll
        for (int nf = 0; nf < 2; nf++)
            wmma::fill_fragment(acc[mf][nf], 0.0f);

    uint4 pAh0, pAh1, pAl0, pAl1, pBh0, pBh1, pBl0, pBl1;
    pAh0 = *reinterpret_cast<const uint4*>(Ahi_g + aoff0);
    pAh1 = *reinterpret_cast<const uint4*>(Ahi_g + aoff1);
    pAl0 = *reinterpret_cast<const uint4*>(Alo_g + aoff0);
    pAl1 = *reinterpret_cast<const uint4*>(Alo_g + aoff1);
    pBh0 = *reinterpret_cast<const uint4*>(Bhi_e + boff0);
    pBh1 = *reinterpret_cast<const uint4*>(Bhi_e + boff1);
    pBl0 = *reinterpret_cast<const uint4*>(Blo_e + boff0);
    pBl1 = *reinterpret_cast<const uint4*>(Blo_e + boff1);

    for (int c = 0; c < NCH; c++) {
        __syncthreads();   // previous chunk's reads complete
        *reinterpret_cast<uint4*>(sAh + s0) = pAh0;
        *reinterpret_cast<uint4*>(sAh + s1) = pAh1;
        *reinterpret_cast<uint4*>(sAl + s0) = pAl0;
        *reinterpret_cast<uint4*>(sAl + s1) = pAl1;
        *reinterpret_cast<uint4*>(sBh + s0) = pBh0;
        *reinterpret_cast<uint4*>(sBh + s1) = pBh1;
        *reinterpret_cast<uint4*>(sBl + s0) = pBl0;
        *reinterpret_cast<uint4*>(sBl + s1) = pBl1;
        __syncthreads();

        if (c + 1 < NCH) {
            int k0 = (c + 1) * KC;
            pAh0 = *reinterpret_cast<const uint4*>(Ahi_g + aoff0 + k0);
            pAh1 = *reinterpret_cast<const uint4*>(Ahi_g + aoff1 + k0);
            pAl0 = *reinterpret_cast<const uint4*>(Alo_g + aoff0 + k0);
            pAl1 = *reinterpret_cast<const uint4*>(Alo_g + aoff1 + k0);
            pBh0 = *reinterpret_cast<const uint4*>(Bhi_e + boff0 + k0);
            pBh1 = *reinterpret_cast<const uint4*>(Bhi_e + boff1 + k0);
            pBl0 = *reinterpret_cast<const uint4*>(Blo_e + boff0 + k0);
            pBl1 = *reinterpret_cast<const uint4*>(Blo_e + boff1 + k0);
        }

#pragma unroll
        for (int kf = 0; kf < 2; kf++) {
            wmma::fragment<wmma::matrix_a, 16, 16, 16, __nv_bfloat16, wmma::row_major> aH[4], aL[4];
            wmma::fragment<wmma::matrix_b, 16, 16, 16, __nv_bfloat16, wmma::col_major> bH[2], bL[2];
#pragma unroll
            for (int mf = 0; mf < 4; mf++) {
                const __nv_bfloat16* ap = sAh + (wm * 64 + mf * 16) * PADK + kf * 16;
                wmma::load_matrix_sync(aH[mf], ap, PADK);
                wmma::load_matrix_sync(aL[mf], ap + SBUF, PADK);   // sAl = sAh + SBUF
            }
#pragma unroll
            for (int nf = 0; nf < 2; nf++) {
                const __nv_bfloat16* bp = sBh + (wn * 32 + nf * 16) * PADK + kf * 16;
                wmma::load_matrix_sync(bH[nf], bp, PADK);
                wmma::load_matrix_sync(bL[nf], bp + SBUF, PADK);   // sBl = sBh + SBUF
            }
#pragma unroll
            for (int mf = 0; mf < 4; mf++)
#pragma unroll
                for (int nf = 0; nf < 2; nf++) {
                    wmma::mma_sync(acc[mf][nf], aH[mf], bH[nf], acc[mf][nf]);
                    wmma::mma_sync(acc[mf][nf], aH[mf], bL[nf], acc[mf][nf]);
                    wmma::mma_sync(acc[mf][nf], aL[mf], bH[nf], acc[mf][nf]);
                }
        }
    }

    // --- epilogue: stage each fragment through smem scratch --------------------
    __syncthreads();
    float* scr = reinterpret_cast<float*>(sm) + wid * 16 * 20;   // 16x16, ldm=20
    const float* be = bias + (size_t)e * NDIM;
    int lrow = lane >> 1;
    int lcol = (lane & 1) * 8;
#pragma unroll
    for (int mf = 0; mf < 4; mf++) {
#pragma unroll
        for (int nf = 0; nf < 2; nf++) {
            wmma::store_matrix_sync(scr, acc[mf][nf], 20, wmma::mem_row_major);
            __syncwarp();
            int r = m0 + wm * 64 + mf * 16 + lrow;
            if (r < cnt) {
                int col = n0 + wn * 32 + nf * 16 + lcol;
                size_t drow;
                if (MODE == 1) drow = (size_t)(roff + r) * NDIM;
                else drow = (size_t)g_rows_dest[roff + r] * NDIM;
#pragma unroll
                for (int j = 0; j < 8; j += 2) {
                    float v0 = scr[lrow * 20 + lcol + j]     + be[col + j];
                    float v1 = scr[lrow * 20 + lcol + j + 1] + be[col + j + 1];
                    if (MODE == 1) {
                        v0 = gelu_exact(v0);
                        v1 = gelu_exact(v1);
                        uint16_t h0, l0, h1, l1;
                        bsplit(v0, h0, l0);
                        bsplit(v1, h1, l1);
                        *reinterpret_cast<uint32_t*>(g_hhi + drow + col + j) =
                            (uint32_t)h0 | ((uint32_t)h1 << 16);
                        *reinterpret_cast<uint32_t*>(g_hlo + drow + col + j) =
                            (uint32_t)l0 | ((uint32_t)l1 << 16);
                    } else {
                        *reinterpret_cast<float2*>(g_oscr + drow + col + j) =
                            make_float2(v0, v1);
                    }
                }
            }
            __syncwarp();
        }
    }
}

// ---------------- check kernels -------------------------------------------------
__global__ void check_h_kernel() {
    size_t idx = ((size_t)blockIdx.x * blockDim.x + threadIdx.x) * 8192;
    if (idx < (size_t)NROWS * HDIM) {
        if (__bfloat16_as_ushort(g_hhi[idx]) != 0) g_flag1 = 0;
    }
}
__global__ void check_o_kernel() {
    size_t idx = ((size_t)blockIdx.x * blockDim.x + threadIdx.x) * 2048;
    if (idx < (size_t)NROWS * DDIM) {
        if (g_oscr[idx] != 0.0f) g_flag2 = 0;
    }
}

// ---------------- FALLBACK SIMT GEMMs (R1-proven structure) ---------------------
template <int MODE>
__global__ __launch_bounds__(256)
void fb_gemm(const float* __restrict__ Aparam,
             const float* __restrict__ Bmat,
             const float* __restrict__ bias) {
    if ((MODE == 1 ? g_flag1 : g_flag2) == 0) return;   // fast path succeeded

    constexpr int KDIM = (MODE == 1) ? DDIM : HDIM;
    constexpr int NDIM = (MODE == 1) ? HDIM : DDIM;

    int e = blockIdx.z;
    int roff = g_offsets[e];
    int cnt = g_offsets[e + 1] - roff;
    int m0 = blockIdx.y * FBM;
    if (m0 >= cnt) return;
    int n0 = blockIdx.x * FBN;

    const float* Bexp = Bmat + (size_t)e * KDIM * NDIM;
    const float* bexp = bias + (size_t)e * NDIM;

    __shared__ float As[FBK][FBM];
    __shared__ float Bs[FBK][FBN];
    __shared__ int rowsrc[FBM];

    int tid = threadIdx.x;
    if (tid < FBM) {
        int r = m0 + tid;
        int src = -1;
        if (r < cnt) src = (MODE == 1) ? g_rows_token[roff + r] : (roff + r);
        rowsrc[tid] = src;
    }
    __syncthreads();

    float acc[8][8];
#pragma unroll
    for (int i = 0; i < 8; i++)
#pragma unroll
        for (int j = 0; j < 8; j++) acc[i][j] = 0.f;

    int ty = tid >> 4, tx = tid & 15;

    for (int k0 = 0; k0 < KDIM; k0 += FBK) {
#pragma unroll
        for (int p = 0; p < 2; p++) {
            int row = (tid >> 2) + p * 64;
            int c4 = (tid & 3) * 4;
            int src = rowsrc[row];
            float f0 = 0.f, f1 = 0.f, f2 = 0.f, f3 = 0.f;
            if (src >= 0) {
                if (MODE == 1) {
                    float4 v = *reinterpret_cast<const float4*>(
                        Aparam + (size_t)src * KDIM + k0 + c4);
                    f0 = v.x; f1 = v.y; f2 = v.z; f3 = v.w;
                } else {
                    uint2 vh = *reinterpret_cast<const uint2*>(g_hhi + (size_t)src * KDIM + k0 + c4);
                    uint2 vl = *reinterpret_cast<const uint2*>(g_hlo + (size_t)src * KDIM + k0 + c4);
                    f0 = bf_lo(vh.x) + bf_lo(vl.x);
                    f1 = bf_hi(vh.x) + bf_hi(vl.x);
                    f2 = bf_lo(vh.y) + bf_lo(vl.y);
                    f3 = bf_hi(vh.y) + bf_hi(vl.y);
                }
            }
            As[c4 + 0][row] = f0;
            As[c4 + 1][row] = f1;
            As[c4 + 2][row] = f2;
            As[c4 + 3][row] = f3;
        }
#pragma unroll
        for (int p = 0; p < 2; p++) {
            int brow2 = (tid >> 5) + p * 8;
            int bc = (tid & 31) * 4;
            float4 v = *reinterpret_cast<const float4*>(
                Bexp + (size_t)(k0 + brow2) * NDIM + n0 + bc);
            *reinterpret_cast<float4*>(&Bs[brow2][bc]) = v;
        }
        __syncthreads();

#pragma unroll
        for (int kk = 0; kk < FBK; kk++) {
            float a[8], b[8];
#pragma unroll
            for (int i = 0; i < 8; i++) a[i] = As[kk][ty * 8 + i];
#pragma unroll
            for (int j = 0; j < 8; j++) b[j] = Bs[kk][tx * 8 + j];
#pragma unroll
            for (int i = 0; i < 8; i++)
#pragma unroll
                for (int j = 0; j < 8; j++)
                    acc[i][j] = fmaf(a[i], b[j], acc[i][j]);
        }
        __syncthreads();
    }

#pragma unroll
    for (int i = 0; i < 8; i++) {
        int r = m0 + ty * 8 + i;
        if (r >= cnt) continue;
#pragma unroll
        for (int j = 0; j < 8; j++) {
            int col = n0 + tx * 8 + j;
            float v = acc[i][j] + bexp[col];
            if (MODE == 1) {
                v = gelu_exact(v);
                uint16_t h, l;
                bsplit(v, h, l);
                size_t o = (size_t)(roff + r) * NDIM + col;
                g_hhi[o] = __ushort_as_bfloat16(h);
                g_hlo[o] = __ushort_as_bfloat16(l);
            } else {
                int slot = g_rows_dest[roff + r];
                g_oscr[(size_t)slot * NDIM + col] = v;
            }
        }
    }
}

// ---------------- combine ------------------------------------------------------
__global__ void combine_kernel(float* __restrict__ y) {
    int idx = blockIdx.x * blockDim.x + threadIdx.x;
    if (idx >= NTOK * DDIM) return;
    int t = idx >> 10;
    int d = idx & (DDIM - 1);
    float w0 = g_wslot[t * 2 + 0];
    float w1 = g_wslot[t * 2 + 1];
    float v0 = g_oscr[(size_t)(t * 2 + 0) * DDIM + d];
    float v1 = g_oscr[(size_t)(t * 2 + 1) * DDIM + d];
    y[idx] = fmaf(w0, v0, w1 * v1);
}

// ---------------- launch -------------------------------------------------------
extern "C" void kernel_launch(void* const* d_in, const int* in_sizes, int n_in,
                              void* d_out, int out_size) {
    const float* x  = (const float*)d_in[0];  // [B,S,D]
    const float* gw = (const float*)d_in[1];  // [D,E]
    const float* w1 = (const float*)d_in[2];  // [E,D,H]
    const float* b1 = (const float*)d_in[3];  // [E,H]
    const float* w2 = (const float*)d_in[4];  // [E,H,D]
    const float* b2 = (const float*)d_in[5];  // [E,D]
    float* y = (float*)d_out;

    reset_kernel<<<1, 32>>>();
    gate_kernel<<<NTOK / 8, 256>>>(x, gw);
    scan_kernel<<<1, 1>>>();
    build_kernel<<<NTOK / 256, 256>>>();

    split_x_kernel<<<(NTOK * DDIM / 4) / 256, 256>>>(x);
    split_wT_kernel<<<dim3(HDIM / 32, DDIM / 32, NEXP), dim3(32, 8)>>>(w1, g_w1hi, g_w1lo, DDIM, HDIM);
    split_wT_kernel<<<dim3(DDIM / 32, HDIM / 32, NEXP), dim3(32, 8)>>>(w2, g_w2hi, g_w2lo, HDIM, DDIM);

    int ntiles = NROWS / TM + NEXP;   // upper bound on total m-tiles

    // fast GEMM1 (wmma) + self-check + fallback
    moe_gemm_wmma<1><<<dim3(HDIM / TN, ntiles, 1), 256>>>(b1);
    check_h_kernel<<<32, 256>>>();
    fb_gemm<1><<<dim3(HDIM / FBN, NROWS / FBM, NEXP), 256>>>(x, w1, b1);

    // fast GEMM2 (wmma) + self-check + fallback
    moe_gemm_wmma<2><<<dim3(DDIM / TN, ntiles, 1), 256>>>(b2);
    check_o_kernel<<<32, 256>>>();
    fb_gemm<2><<<dim3(DDIM / FBN, NROWS / FBM, NEXP), 256>>>(nullptr, w2, b2);

    combine_kernel<<<(NTOK * DDIM) / 256, 256>>>(y);
}